// round 10
// baseline (speedup 1.0000x reference)
#include <cuda_runtime.h>
#include <cuda_fp16.h>

#define BATCH   256
#define IN_DIM  65536
#define OUT_DIM 65536

#define NB_T 2048   // transpose tiles: (IN/128) x (B/64)
#define NB_C 256
#define NB_I 512
#define NTILES 2048 // main tiles: 32 neurons each

// ---------------- device scratch ----------------------------------------
__device__ float4 g_coef[OUT_DIM];                             // 1 MB
__device__ __align__(16) __half g_xth[(size_t)IN_DIM * BATCH]; // 32 MB
__device__ int    g_idx[2 * OUT_DIM];                          // 512 KB

// ---------------- fused prep: transpose + coef + idx (R6, proven) -------
__global__ __launch_bounds__(256) void prep_kernel(const float* __restrict__ x,
                                                   const float* __restrict__ wts,
                                                   const void*  __restrict__ idxraw) {
    __shared__ float t[4][64][33];
    int bx  = blockIdx.x;
    int tid = threadIdx.x;

    if (bx < NB_T) {
        int it = bx & 511, bt = bx >> 9;
        int i0 = it * 128, b0 = bt * 64;
        int tx = tid & 7, ty = tid >> 3;

        const float4* r0 = (const float4*)(x + (size_t)(b0 + ty)      * IN_DIM + i0);
        const float4* r1 = (const float4*)(x + (size_t)(b0 + 32 + ty) * IN_DIM + i0);
        float4 v0[4], v1[4];
        #pragma unroll
        for (int h = 0; h < 4; h++) {
            v0[h] = __ldcs(r0 + tx + 8 * h);
            v1[h] = __ldcs(r1 + tx + 8 * h);
        }
        #pragma unroll
        for (int h = 0; h < 4; h++) {
            t[h][ty   ][tx*4+0]=v0[h].x; t[h][ty   ][tx*4+1]=v0[h].y;
            t[h][ty   ][tx*4+2]=v0[h].z; t[h][ty   ][tx*4+3]=v0[h].w;
            t[h][ty+32][tx*4+0]=v1[h].x; t[h][ty+32][tx*4+1]=v1[h].y;
            t[h][ty+32][tx*4+2]=v1[h].z; t[h][ty+32][tx*4+3]=v1[h].w;
        }
        __syncthreads();
        #pragma unroll
        for (int h = 0; h < 4; h++) {
            union { uint4 u; __half2 hh[4]; } pk;
            #pragma unroll
            for (int k = 0; k < 4; k++)
                pk.hh[k] = __floats2half2_rn(t[h][8*tx + 2*k][ty], t[h][8*tx + 2*k + 1][ty]);
            *(uint4*)(g_xth + (size_t)(i0 + 32*h + ty) * BATCH + b0 + 8*tx) = pk.u;
        }
    } else if (bx < NB_T + NB_C) {
        int o = (bx - NB_T) * 256 + tid;
        float p[16];
        const float4* w4 = (const float4*)(wts + (size_t)o * 16);
        float4 q0 = w4[0], q1 = w4[1], q2 = w4[2], q3 = w4[3];
        p[0]=q0.x; p[1]=q0.y; p[2]=q0.z; p[3]=q0.w;
        p[4]=q1.x; p[5]=q1.y; p[6]=q1.z; p[7]=q1.w;
        p[8]=q2.x; p[9]=q2.y; p[10]=q2.z; p[11]=q2.w;
        p[12]=q3.x; p[13]=q3.y; p[14]=q3.z; p[15]=q3.w;
        float m = p[0];
        #pragma unroll
        for (int i = 1; i < 16; i++) m = fmaxf(m, p[i]);
        float s = 0.f;
        #pragma unroll
        for (int i = 0; i < 16; i++) { p[i] = __expf(p[i] - m); s += p[i]; }
        float inv = 1.0f / s;
        #pragma unroll
        for (int i = 0; i < 16; i++) p[i] *= inv;
        float4 c;
        c.x = p[8]+p[9]+p[10]+p[11]+p[12]+p[13]+p[14]+p[15];
        c.y = p[2]+p[3]+p[6]+p[7]-p[8]-p[9]-p[12]-p[13];
        c.z = p[4]+p[5]+p[6]+p[7]-p[8]-p[9]-p[10]-p[11];
        c.w = p[1]-p[2]-p[4]-2.f*p[6]-p[7]+p[8]+2.f*p[9]+p[11]+p[13]-p[14];
        g_coef[o] = c;
    } else {
        __shared__ int s64;
        if (tid == 0) {
            const long long* p = (const long long*)idxraw;
            int is64 = 1;
            #pragma unroll 1
            for (int j = 0; j < 64; j++) {
                long long v = p[j];
                if (v < 0 || v >= IN_DIM) { is64 = 0; break; }
            }
            s64 = is64;
        }
        __syncthreads();
        int i = (bx - NB_T - NB_C) * 256 + tid;
        g_idx[i] = s64 ? (int)((const long long*)idxraw)[i]
                       : ((const int*)idxraw)[i];
    }
}

// ---------------- main: cp.async double-buffered pipeline ---------------
// Tile = 32 neurons x 256 batches. Stage buffers hold the tile's 64 gather
// rows (32KB); while tile t is computed, tile t+grid's rows stream in via
// cp.async.cg (no registers, no LDG scoreboard limit).

// issue one tile's 64 rows (512B each) into stage buffer at smem addr 'dst'
__device__ __forceinline__ void issue_tile(unsigned dst, int tile, int tid) {
    int ob  = tile * 32;
    int w   = tid >> 5;        // 0..7
    int col = tid & 31;        // 16B chunk within row
    const char* base = (const char*)g_xth;
    #pragma unroll
    for (int j = 0; j < 4; j++) {
        int n = w + 8 * j;     // neuron row group (uniform within warp)
        unsigned ra = (unsigned)__ldg(&g_idx[ob + n]);
        unsigned rb = (unsigned)__ldg(&g_idx[OUT_DIM + ob + n]);
        const char* pa = base + (size_t)ra * 512 + col * 16;
        const char* pb = base + (size_t)rb * 512 + col * 16;
        unsigned da = dst + (unsigned)(n * 512 + col * 16);
        unsigned db = dst + (unsigned)((32 + n) * 512 + col * 16);
        asm volatile("cp.async.cg.shared.global [%0], [%1], 16;" :: "r"(da), "l"(pa));
        asm volatile("cp.async.cg.shared.global [%0], [%1], 16;" :: "r"(db), "l"(pb));
    }
    asm volatile("cp.async.commit_group;");
}

__device__ __forceinline__ void compute_tile(const __half* stg, float* so,
                                             float* __restrict__ out,
                                             int tile, int tid) {
    int w = tid >> 5, l = tid & 31;
    int ob = tile * 32;
    #pragma unroll
    for (int c = 0; c < 4; c++) {
        int n = 4 * w + c;                       // local neuron
        float4 cf = __ldg(&g_coef[ob + n]);
        union { uint4 u; __half2 h[4]; } A, B;
        A.u = *(const uint4*)((const char*)stg + n * 512 + 16 * l);
        B.u = *(const uint4*)((const char*)stg + (32 + n) * 512 + 16 * l);
        int col = (n + l) & 31;                  // store bank l+const: bijective
        #pragma unroll
        for (int k = 0; k < 4; k++) {
            float2 a = __half22float2(A.h[k]);
            float2 b = __half22float2(B.h[k]);
            int bb = 8 * l + 2 * k;
            so[bb * 32 + col]       = fmaf(fmaf(cf.w, b.x, cf.y), a.x, fmaf(cf.z, b.x, cf.x));
            so[(bb + 1) * 32 + col] = fmaf(fmaf(cf.w, b.y, cf.y), a.y, fmaf(cf.z, b.y, cf.x));
        }
    }
    __syncthreads();
    // warp w writes batch rows 32w..32w+31; 128B-coalesced streaming stores
    #pragma unroll
    for (int j = 0; j < 32; j++) {
        int bb = w * 32 + j;
        __stcs(out + (size_t)bb * OUT_DIM + ob + l,
               so[bb * 32 + ((l + (bb >> 3)) & 31)]);
    }
}

__global__ __launch_bounds__(256) void logic_main_kernel(float* __restrict__ out) {
    extern __shared__ __align__(16) char sm[];
    __half* st0 = (__half*)sm;                 // 32 KB
    __half* st1 = (__half*)(sm + 32768);       // 32 KB
    float*  so  = (float*)(sm + 65536);        // 32 KB
    unsigned a0 = (unsigned)__cvta_generic_to_shared(st0);
    unsigned a1 = (unsigned)__cvta_generic_to_shared(st1);
    int tid = threadIdx.x;
    int gsz = gridDim.x;

    int t = blockIdx.x;
    issue_tile(a0, t, tid);
    int sid = 0;
    #pragma unroll 1
    for (; t < NTILES; t += gsz) {
        int tn = t + gsz;
        if (tn < NTILES) {
            issue_tile(sid ? a0 : a1, tn, tid);
            asm volatile("cp.async.wait_group 1;");
        } else {
            asm volatile("cp.async.wait_group 0;");
        }
        __syncthreads();                        // cp.async data + so-reuse order
        compute_tile(sid ? st1 : st0, so, out, t, tid);
        sid ^= 1;
    }
}

// ---------------- launch ------------------------------------------------
extern "C" void kernel_launch(void* const* d_in, const int* in_sizes, int n_in,
                              void* d_out, int out_size) {
    const float* x   = (const float*)d_in[0];
    const float* wts = (const float*)d_in[1];
    const void*  idx = d_in[2];
    float* out = (float*)d_out;

    int dev = 0, sms = 148;
    cudaGetDevice(&dev);
    cudaDeviceGetAttribute(&sms, cudaDevAttrMultiProcessorCount, dev);
    int grid = 2 * sms;
    if (grid > NTILES) grid = NTILES;

    static int smem_set = 0;
    if (!smem_set) {
        cudaFuncSetAttribute(logic_main_kernel,
                             cudaFuncAttributeMaxDynamicSharedMemorySize, 98304);
        smem_set = 1;
    }

    prep_kernel<<<NB_T + NB_C + NB_I, 256>>>(x, wts, idx);
    logic_main_kernel<<<grid, 256, 98304>>>(out);
}

// round 11
// speedup vs baseline: 1.0007x; 1.0007x over previous
#include <cuda_runtime.h>
#include <cuda_fp16.h>

#define BATCH   256
#define IN_DIM  65536
#define OUT_DIM 65536

#define NB_T 2048   // transpose tiles: (IN/128) x (B/64)

// ---------------- device scratch ----------------------------------------
__device__ __align__(16) __half g_xth[(size_t)IN_DIM * BATCH]; // 32 MB

// ---------------- prep: pure transpose x[B][IN] f32 -> xt[IN][B] f16 ----
__global__ __launch_bounds__(256) void prep_kernel(const float* __restrict__ x) {
    __shared__ float t[4][64][33];
    int bx  = blockIdx.x;
    int tid = threadIdx.x;

    int it = bx & 511, bt = bx >> 9;
    int i0 = it * 128, b0 = bt * 64;
    int tx = tid & 7, ty = tid >> 3;

    const float4* r0 = (const float4*)(x + (size_t)(b0 + ty)      * IN_DIM + i0);
    const float4* r1 = (const float4*)(x + (size_t)(b0 + 32 + ty) * IN_DIM + i0);
    float4 v0[4], v1[4];
    #pragma unroll
    for (int h = 0; h < 4; h++) {
        v0[h] = __ldcs(r0 + tx + 8 * h);
        v1[h] = __ldcs(r1 + tx + 8 * h);
    }
    #pragma unroll
    for (int h = 0; h < 4; h++) {
        t[h][ty   ][tx*4+0]=v0[h].x; t[h][ty   ][tx*4+1]=v0[h].y;
        t[h][ty   ][tx*4+2]=v0[h].z; t[h][ty   ][tx*4+3]=v0[h].w;
        t[h][ty+32][tx*4+0]=v1[h].x; t[h][ty+32][tx*4+1]=v1[h].y;
        t[h][ty+32][tx*4+2]=v1[h].z; t[h][ty+32][tx*4+3]=v1[h].w;
    }
    __syncthreads();
    #pragma unroll
    for (int h = 0; h < 4; h++) {
        union { uint4 u; __half2 hh[4]; } pk;
        #pragma unroll
        for (int k = 0; k < 4; k++)
            pk.hh[k] = __floats2half2_rn(t[h][8*tx + 2*k][ty], t[h][8*tx + 2*k + 1][ty]);
        *(uint4*)(g_xth + (size_t)(i0 + 32*h + ty) * BATCH + b0 + 8*tx) = pk.u;
    }
}

// ---------------- main: 8 warps x 4 neurons, fully self-contained -------
// Each warp: detects idx dtype (ballot over 16 probe reads), loads its own
// 8 row indices, computes its own 4 softmax-collapsed coefficient vectors
// (streaming, no max-subtraction: |w|max ~ 5.3 so expf is safe), gathers
// 8 full 512B fp16 rows (MLP=8), then computes + stages + writes exactly
// as the proven R4 kernel.
#define SWZ(b) ((20 * (((b) >> 2) & 7) + (((b) >> 5) & 7)) & 31)

// per-op coefficients of the bilinear collapse: op = k0 + k1*a + k2*b + k3*ab
__constant__ float K0[16] = {0,0,0,0, 0,0,0,0, 1,1,1,1, 1,1,1,1};
__constant__ float K1[16] = {0,0,1,1, 0,0,1,1, -1,-1,0,0, -1,-1,0,0};
__constant__ float K2[16] = {0,0,0,0, 1,1,1,1, -1,-1,-1,-1, 0,0,0,0};
__constant__ float K3[16] = {0,1,-1,0, -1,0,-2,-1, 1,2,0,1, 0,1,-1,0};

__global__ __launch_bounds__(256, 4) void logic_main_kernel(
        const float* __restrict__ wts,
        const void*  __restrict__ idxraw,
        float* __restrict__ out) {
    __shared__ float s[BATCH * 32];           // 32 KB
    int tid = threadIdx.x;
    int w = tid >> 5, l = tid & 31;
    int ob = blockIdx.x * 32;
    int n0 = w * 4;

    // ---- per-warp idx dtype detection ----
    const long long* pll = (const long long*)idxraw;
    long long dv = __ldg(&pll[l & 15]);
    unsigned badmask = __ballot_sync(0xffffffffu, dv < 0 || dv >= IN_DIM);
    bool is64 = (badmask == 0u);

    // ---- lanes 0-7 load this warp's 8 row indices ----
    int rowidx = 0;
    {
        int c = l & 3;
        int pos = (l & 4) ? (OUT_DIM + ob + n0 + c) : (ob + n0 + c);
        if (l < 8)
            rowidx = is64 ? (int)__ldg(&pll[pos])
                          : __ldg(&((const int*)idxraw)[pos]);
    }

    // ---- coef for neuron n0 + (l&3): streaming softmax collapse ----
    float4 my;
    {
        int o = ob + n0 + (l & 3);
        const float* wr = wts + (size_t)o * 16;
        float sum = 0.f, cx = 0.f, cy = 0.f, cz = 0.f, cw = 0.f;
        #pragma unroll
        for (int i = 0; i < 16; i++) {
            float e = __expf(__ldg(wr + i));
            sum += e;
            cx = fmaf(K0[i], e, cx);
            cy = fmaf(K1[i], e, cy);
            cz = fmaf(K2[i], e, cz);
            cw = fmaf(K3[i], e, cw);
        }
        float inv = 1.0f / sum;
        my = make_float4(cx * inv, cy * inv, cz * inv, cw * inv);
    }

    // ---- gather all 8 rows (512B each), MLP = 8 ----
    const char* base = (const char*)g_xth;
    unsigned lane16 = (unsigned)l * 16u;
    uint4 va[4], vb[4];
    #pragma unroll
    for (int c = 0; c < 4; c++) {
        unsigned ra = (unsigned)__shfl_sync(0xffffffffu, rowidx, c);
        unsigned rb = (unsigned)__shfl_sync(0xffffffffu, rowidx, 4 + c);
        va[c] = *(const uint4*)(base + (size_t)ra * 512u + lane16);
        vb[c] = *(const uint4*)(base + (size_t)rb * 512u + lane16);
    }

    // ---- compute + swizzled staging (R4-proven) ----
    #pragma unroll
    for (int c = 0; c < 4; c++) {
        float4 cf;
        cf.x = __shfl_sync(0xffffffffu, my.x, c);
        cf.y = __shfl_sync(0xffffffffu, my.y, c);
        cf.z = __shfl_sync(0xffffffffu, my.z, c);
        cf.w = __shfl_sync(0xffffffffu, my.w, c);
        union { uint4 u; __half2 h[4]; } A, Bv;
        A.u = va[c]; Bv.u = vb[c];
        int n = n0 + c;
        int bbase = 8 * l;
        #pragma unroll
        for (int k2 = 0; k2 < 4; k2++) {
            float2 a = __half22float2(A.h[k2]);
            float2 b = __half22float2(Bv.h[k2]);
            float v0 = fmaf(fmaf(cf.w, b.x, cf.y), a.x, fmaf(cf.z, b.x, cf.x));
            float v1 = fmaf(fmaf(cf.w, b.y, cf.y), a.y, fmaf(cf.z, b.y, cf.x));
            int b0i = bbase + 2 * k2;
            int b1i = b0i + 1;
            s[b0i * 32 + ((n + SWZ(b0i)) & 31)] = v0;
            s[b1i * 32 + ((n + SWZ(b1i)) & 31)] = v1;
        }
    }
    __syncthreads();

    // ---- 128B-coalesced streaming output ----
    #pragma unroll
    for (int j = 0; j < 32; j++) {
        int b = w * 32 + j;
        __stcs(out + (size_t)b * OUT_DIM + ob + l,
               s[b * 32 + ((l + SWZ(b)) & 31)]);
    }
}

// ---------------- launch ------------------------------------------------
extern "C" void kernel_launch(void* const* d_in, const int* in_sizes, int n_in,
                              void* d_out, int out_size) {
    const float* x   = (const float*)d_in[0];
    const float* wts = (const float*)d_in[1];
    const void*  idx = d_in[2];
    float* out = (float*)d_out;

    prep_kernel<<<NB_T, 256>>>(x);
    logic_main_kernel<<<OUT_DIM / 32, 256>>>(wts, idx, out);
}